// round 1
// baseline (speedup 1.0000x reference)
#include <cuda_runtime.h>
#include <math.h>

#define NB   100
#define NPG  500
#define NN   (NB*NPG)     // 50000 nodes
#define NE   (NN*12)      // 600000 edges
#define H    128
#define K1   250
#define K2   125
#define K3   63

// ---------------- scratch (device globals; no allocation) ----------------
__device__ float g_h   [NN*H];
__device__ float g_h2  [NN*H];
__device__ float g_agg [NN*H];
__device__ float g_cnt [NN];
__device__ float g_score[NN];
__device__ int   g_map [NN];
__device__ int   g_perm[NB*K1];
__device__ int   g_src [NE];
__device__ int   g_dst [NE];
__device__ float g_z   [NB*2*H];

// ---------------- kernels ----------------

__global__ void k_copy_edges(const int* __restrict__ ei) {
    int i = blockIdx.x * blockDim.x + threadIdx.x;
    if (i < NE) { g_src[i] = ei[i]; g_dst[i] = ei[NE + i]; }
}

__global__ void k_zero(float* __restrict__ p, int n) {
    int i = blockIdx.x * blockDim.x + threadIdx.x;
    int stride = gridDim.x * blockDim.x;
    for (; i < n; i += stride) p[i] = 0.0f;
}

// one warp per edge; lane handles 4 consecutive floats
__global__ void k_scatter(const float* __restrict__ xin) {
    int gid  = blockIdx.x * blockDim.x + threadIdx.x;
    int e    = gid >> 5;
    int lane = gid & 31;
    if (e >= NE) return;
    int s = g_src[e];
    if (s < 0) return;           // masked edge
    int d = g_dst[e];
    const float4 v = reinterpret_cast<const float4*>(xin + (size_t)s * H)[lane];
    float* ag = g_agg + (size_t)d * H + lane * 4;
    atomicAdd(ag + 0, v.x);
    atomicAdd(ag + 1, v.y);
    atomicAdd(ag + 2, v.z);
    atomicAdd(ag + 3, v.w);
    if (lane == 0) atomicAdd(&g_cnt[d], 1.0f);
}

// out = relu( (agg/max(cnt,1)) @ Wl + bl + xin @ Wr )
// Both 128x128 weights resident in shared; 256 threads -> 2 rows per iter.
__global__ void k_sage(const float* __restrict__ xin,
                       const float* __restrict__ Wl, const float* __restrict__ bl,
                       const float* __restrict__ Wr,
                       float* __restrict__ out, int n) {
    extern __shared__ float sh[];
    float* sWl = sh;
    float* sWr = sh + H * H;
    float* sb  = sh + 2 * H * H;
    float* sin = sb + H;                // 2 rows x (mean|x) = 512 floats
    int tid = threadIdx.x;
    for (int i = tid; i < H * H; i += blockDim.x) { sWl[i] = Wl[i]; sWr[i] = Wr[i]; }
    if (tid < H) sb[tid] = bl[tid];
    __syncthreads();

    int rr  = tid >> 7;                 // 0 or 1: which row of the pair
    int col = tid & 127;

    for (int row0 = blockIdx.x * 2; row0 < n; row0 += gridDim.x * 2) {
        int row = row0 + rr;
        float m = 0.0f, xv = 0.0f;
        if (row < n) {
            float c = g_cnt[row];
            c = c > 1.0f ? c : 1.0f;
            m  = g_agg[(size_t)row * H + col] / c;
            xv = xin[(size_t)row * H + col];
        }
        __syncthreads();                // prior iter readers done
        sin[rr * 2 * H + col]     = m;
        sin[rr * 2 * H + H + col] = xv;
        __syncthreads();

        const float* a = &sin[rr * 2 * H];
        const float* b = a + H;
        float a0 = sb[col], a1 = 0.f, a2 = 0.f, a3 = 0.f;
        #pragma unroll
        for (int k = 0; k < H; k += 4) {
            a0 += a[k]     * sWl[(k)     * H + col];
            a1 += a[k + 1] * sWl[(k + 1) * H + col];
            a2 += a[k + 2] * sWl[(k + 2) * H + col];
            a3 += a[k + 3] * sWl[(k + 3) * H + col];
        }
        #pragma unroll
        for (int k = 0; k < H; k += 4) {
            a0 += b[k]     * sWr[(k)     * H + col];
            a1 += b[k + 1] * sWr[(k + 1) * H + col];
            a2 += b[k + 2] * sWr[(k + 2) * H + col];
            a3 += b[k + 3] * sWr[(k + 3) * H + col];
        }
        if (row < n) {
            float v = (a0 + a1) + (a2 + a3);
            out[(size_t)row * H + col] = v > 0.0f ? v : 0.0f;
        }
    }
}

// score = tanh( (h . w) / ||w|| ), one warp per node
__global__ void k_score(const float* __restrict__ h, const float* __restrict__ pw, int n) {
    int gid  = blockIdx.x * blockDim.x + threadIdx.x;
    int node = gid >> 5;
    int lane = gid & 31;
    if (node >= n) return;
    float dot = 0.f, wn = 0.f;
    #pragma unroll
    for (int c = lane; c < H; c += 32) {
        float w = pw[c];
        dot += h[(size_t)node * H + c] * w;
        wn  += w * w;
    }
    #pragma unroll
    for (int o = 16; o; o >>= 1) {
        dot += __shfl_down_sync(0xffffffffu, dot, o);
        wn  += __shfl_down_sync(0xffffffffu, wn, o);
    }
    if (lane == 0) g_score[node] = tanhf(dot / sqrtf(wn));
}

// stable top-k per graph via rank counting (matches jax.lax.top_k tie-break)
__global__ void k_topk(int n_per, int k) {
    int b = blockIdx.x;
    __shared__ float s[512];
    int i = threadIdx.x;
    s[i] = (i < n_per) ? g_score[b * n_per + i] : -1e30f;
    __syncthreads();
    if (i < n_per) {
        float si = s[i];
        int rank = 0;
        for (int j = 0; j < n_per; j++) {
            float sj = s[j];
            if (sj > si || (sj == si && j < i)) rank++;
        }
        int old = b * n_per + i;
        if (rank < k) {
            int nw = b * k + rank;
            g_map[old]  = nw;
            g_perm[nw]  = old;
        } else {
            g_map[old] = -1;
        }
    }
}

__global__ void k_pool(const float* __restrict__ hin, float* __restrict__ hout, int nnew) {
    int gid = blockIdx.x * blockDim.x + threadIdx.x;
    if (gid >= nnew * H) return;
    int j = gid >> 7, c = gid & 127;
    int old = g_perm[j];
    hout[gid] = hin[(size_t)old * H + c] * g_score[old];
}

__global__ void k_remap() {
    int e = blockIdx.x * blockDim.x + threadIdx.x;
    if (e >= NE) return;
    int s = g_src[e], d = g_dst[e];
    int ns = (s >= 0) ? g_map[s] : -1;
    int nd = (d >= 0) ? g_map[d] : -1;
    if (ns < 0 || nd < 0) { ns = -1; nd = -1; }
    g_src[e] = ns;
    g_dst[e] = nd;
}

// z[b] (+)= [max || mean] over k nodes
__global__ void k_readout(const float* __restrict__ h, int k, int acc) {
    int b = blockIdx.x, c = threadIdx.x;
    float mx = -1e30f, sm = 0.f;
    for (int r = 0; r < k; r++) {
        float v = h[(size_t)(b * k + r) * H + c];
        mx = fmaxf(mx, v);
        sm += v;
    }
    float mean = sm / (float)k;
    if (acc) {
        g_z[b * 2 * H + c]     += mx;
        g_z[b * 2 * H + H + c] += mean;
    } else {
        g_z[b * 2 * H + c]     = mx;
        g_z[b * 2 * H + H + c] = mean;
    }
}

// MLP head + log_softmax, one block per graph
__global__ void k_mlp(const float* __restrict__ W1, const float* __restrict__ b1,
                      const float* __restrict__ W2, const float* __restrict__ b2,
                      const float* __restrict__ W3, const float* __restrict__ b3,
                      float* __restrict__ out) {
    int b = blockIdx.x, t = threadIdx.x;
    __shared__ float zin[256], t1[128], t2[64], lg[10];
    zin[t] = g_z[b * 256 + t];
    __syncthreads();
    if (t < 128) {
        float a = b1[t];
        for (int k = 0; k < 256; k++) a += zin[k] * W1[k * 128 + t];
        t1[t] = fmaxf(a, 0.f);
    }
    __syncthreads();
    if (t < 64) {
        float a = b2[t];
        for (int k = 0; k < 128; k++) a += t1[k] * W2[k * 64 + t];
        t2[t] = fmaxf(a, 0.f);
    }
    __syncthreads();
    if (t < 10) {
        float a = b3[t];
        for (int k = 0; k < 64; k++) a += t2[k] * W3[k * 10 + t];
        lg[t] = a;
    }
    __syncthreads();
    if (t == 0) {
        float mx = -1e30f;
        for (int i = 0; i < 10; i++) mx = fmaxf(mx, lg[i]);
        float s = 0.f;
        for (int i = 0; i < 10; i++) s += expf(lg[i] - mx);
        float lse = mx + logf(s);
        for (int i = 0; i < 10; i++) out[b * 10 + i] = lg[i] - lse;
    }
}

// ---------------- host ----------------

static const int SAGE_SMEM = (2 * H * H + H + 4 * H) * sizeof(float);  // 133632 B

extern "C" void kernel_launch(void* const* d_in, const int* in_sizes, int n_in,
                              void* d_out, int out_size) {
    const float* x   = (const float*)d_in[0];
    const int*   ei  = (const int*)  d_in[1];
    const float* Wl1 = (const float*)d_in[2];
    const float* bl1 = (const float*)d_in[3];
    const float* Wr1 = (const float*)d_in[4];
    const float* Wl2 = (const float*)d_in[5];
    const float* bl2 = (const float*)d_in[6];
    const float* Wr2 = (const float*)d_in[7];
    const float* Wl3 = (const float*)d_in[8];
    const float* bl3 = (const float*)d_in[9];
    const float* Wr3 = (const float*)d_in[10];
    const float* pw1 = (const float*)d_in[11];
    const float* pw2 = (const float*)d_in[12];
    const float* pw3 = (const float*)d_in[13];
    const float* W1  = (const float*)d_in[14];
    const float* b1  = (const float*)d_in[15];
    const float* W2  = (const float*)d_in[16];
    const float* b2  = (const float*)d_in[17];
    const float* W3  = (const float*)d_in[18];
    const float* b3  = (const float*)d_in[19];
    float* out = (float*)d_out;

    cudaFuncSetAttribute(k_sage, cudaFuncAttributeMaxDynamicSharedMemorySize, SAGE_SMEM);

    void *p_h, *p_h2, *p_agg, *p_cnt;
    cudaGetSymbolAddress(&p_h,   g_h);
    cudaGetSymbolAddress(&p_h2,  g_h2);
    cudaGetSymbolAddress(&p_agg, g_agg);
    cudaGetSymbolAddress(&p_cnt, g_cnt);
    float* dh   = (float*)p_h;
    float* dh2  = (float*)p_h2;
    float* dagg = (float*)p_agg;
    float* dcnt = (float*)p_cnt;

    k_copy_edges<<<(NE + 255) / 256, 256>>>(ei);

    struct Layer {
        const float *Wl, *bl, *Wr, *pw;
        int n_in, n_per, k;
    } layers[3] = {
        {Wl1, bl1, Wr1, pw1, NN,      NPG, K1},
        {Wl2, bl2, Wr2, pw2, NB * K1, K1,  K2},
        {Wl3, bl3, Wr3, pw3, NB * K2, K2,  K3},
    };

    const float* xin = x;
    for (int l = 0; l < 3; l++) {
        const Layer& L = layers[l];
        int nH = L.n_in * H;

        k_zero<<<(nH + 255) / 256, 256>>>(dagg, nH);
        k_zero<<<(L.n_in + 255) / 256, 256>>>(dcnt, L.n_in);

        k_scatter<<<(NE * 32 + 255) / 256, 256>>>(xin);

        int gemm_grid = (L.n_in + 1) / 2;
        if (gemm_grid > 148) gemm_grid = 148;
        k_sage<<<gemm_grid, 256, SAGE_SMEM>>>(xin, L.Wl, L.bl, L.Wr, dh, L.n_in);

        k_score<<<(L.n_in * 32 + 255) / 256, 256>>>(dh, L.pw, L.n_in);
        k_topk<<<NB, 512>>>(L.n_per, L.k);

        int nnew = NB * L.k;
        k_pool<<<(nnew * H + 255) / 256, 256>>>(dh, dh2, nnew);

        if (l < 2) k_remap<<<(NE + 255) / 256, 256>>>();

        k_readout<<<NB, H>>>(dh2, L.k, l == 0 ? 0 : 1);

        xin = dh2;   // pooled features feed the next layer
    }

    k_mlp<<<NB, 256>>>(W1, b1, W2, b2, W3, b3, out);
}

// round 2
// speedup vs baseline: 2.5820x; 2.5820x over previous
#include <cuda_runtime.h>
#include <math.h>

#define NB   100
#define NPG  500
#define NN   (NB*NPG)     // 50000 nodes
#define NE   (NN*12)      // 600000 edges
#define H    128
#define K1   250
#define K2   125
#define K3   63

// ---------------- scratch (device globals; no allocation) ----------------
__device__ float g_h    [NN*H];        // pre-pool features
__device__ float g_mean [NN*H];        // gathered mean
__device__ float g_p1   [NB*K1*H];     // pooled buffer A
__device__ float g_p2   [NB*K2*H];     // pooled buffer B
__device__ float g_score[NN];
__device__ int   g_map  [NN];
__device__ int   g_perm [NB*K1];
__device__ int   g_srcB [NE];
__device__ int   g_dstB [NE];
__device__ int   g_srcC [NE];
__device__ int   g_dstC [NE];
__device__ int   g_csr  [NE];
__device__ int   g_deg  [NN];
__device__ int   g_start[NN];
__device__ int   g_cur  [NN];
__device__ int   g_ecnt [3];           // active edge counts per layer
__device__ int   g_gcursor;
__device__ float g_z    [NB*2*H];

// ---------------- f32x2 helpers ----------------
__device__ __forceinline__ unsigned long long pk2(float x, float y) {
    unsigned long long r;
    asm("mov.b64 %0, {%1, %2};" : "=l"(r) : "r"(__float_as_uint(x)), "r"(__float_as_uint(y)));
    return r;
}
__device__ __forceinline__ void upk2(unsigned long long v, float& x, float& y) {
    unsigned a, b;
    asm("mov.b64 {%0, %1}, %2;" : "=r"(a), "=r"(b) : "l"(v));
    x = __uint_as_float(a); y = __uint_as_float(b);
}
#define FMA2(d, a, b) asm("fma.rn.f32x2 %0, %1, %2, %3;" : "=l"(d) : "l"(a), "l"(b), "l"(d))

// ---------------- kernels ----------------

__global__ void k_init() {
    g_ecnt[0] = NE; g_ecnt[1] = 0; g_ecnt[2] = 0;
}

// zero degree array for this layer + reset cursor
__global__ void k_prep(int n) {
    int i = blockIdx.x * blockDim.x + threadIdx.x;
    if (i < n) g_deg[i] = 0;
    if (i == 0) g_gcursor = 0;
}

__global__ void k_degree(const int* __restrict__ dst, const int* __restrict__ ecnt) {
    int e = blockIdx.x * blockDim.x + threadIdx.x;
    if (e < *ecnt) atomicAdd(&g_deg[dst[e]], 1);
}

// allocate contiguous csr ranges per node: warp scan + one atomic per warp
__global__ void k_alloc(int n) {
    int i = blockIdx.x * blockDim.x + threadIdx.x;
    int lane = threadIdx.x & 31;
    int d = (i < n) ? g_deg[i] : 0;
    int x = d;
    #pragma unroll
    for (int o = 1; o < 32; o <<= 1) {
        int y = __shfl_up_sync(0xffffffffu, x, o);
        if (lane >= o) x += y;
    }
    int excl = x - d;
    int total = __shfl_sync(0xffffffffu, x, 31);
    int base = 0;
    if (lane == 31) base = atomicAdd(&g_gcursor, total);
    base = __shfl_sync(0xffffffffu, base, 31);
    if (i < n) { g_start[i] = base + excl; g_cur[i] = base + excl; }
}

__global__ void k_fill(const int* __restrict__ src, const int* __restrict__ dst,
                       const int* __restrict__ ecnt) {
    int e = blockIdx.x * blockDim.x + threadIdx.x;
    if (e < *ecnt) {
        int pos = atomicAdd(&g_cur[dst[e]], 1);
        g_csr[pos] = src[e];
    }
}

// one warp per node: gather neighbor features, write mean
__global__ void k_gather(const float* __restrict__ xin, int n) {
    int gid  = blockIdx.x * blockDim.x + threadIdx.x;
    int node = gid >> 5;
    int lane = gid & 31;
    if (node >= n) return;
    int start = g_start[node];
    int deg   = g_deg[node];
    float4 acc = {0.f, 0.f, 0.f, 0.f};
    int j = 0;
    for (; j + 1 < deg; j += 2) {
        int s0 = g_csr[start + j];
        int s1 = g_csr[start + j + 1];
        float4 v0 = reinterpret_cast<const float4*>(xin + (size_t)s0 * H)[lane];
        float4 v1 = reinterpret_cast<const float4*>(xin + (size_t)s1 * H)[lane];
        acc.x += v0.x; acc.y += v0.y; acc.z += v0.z; acc.w += v0.w;
        acc.x += v1.x; acc.y += v1.y; acc.z += v1.z; acc.w += v1.w;
    }
    if (j < deg) {
        int s0 = g_csr[start + j];
        float4 v0 = reinterpret_cast<const float4*>(xin + (size_t)s0 * H)[lane];
        acc.x += v0.x; acc.y += v0.y; acc.z += v0.z; acc.w += v0.w;
    }
    float inv = 1.0f / fmaxf((float)deg, 1.0f);
    float4 o = {acc.x * inv, acc.y * inv, acc.z * inv, acc.w * inv};
    reinterpret_cast<float4*>(g_mean + (size_t)node * H)[lane] = o;
}

// out = relu( [mean||x] @ [Wl;Wr] + bl ), K=256 fused GEMM, f32x2 packed math
#define TM 64
__global__ void __launch_bounds__(256) k_sage(const float* __restrict__ xin,
                                              const float* __restrict__ Wl,
                                              const float* __restrict__ bl,
                                              const float* __restrict__ Wr,
                                              float* __restrict__ out, int n) {
    extern __shared__ float sh[];
    float* sW  = sh;                    // [256][128]
    float* sIn = sh + 256 * 128;        // [64][256]
    float* sb  = sIn + 64 * 256;        // [128]
    int t = threadIdx.x;
    for (int i = t; i < 128 * 128; i += 256) { sW[i] = Wl[i]; sW[128 * 128 + i] = Wr[i]; }
    if (t < 128) sb[t] = bl[t];
    __syncthreads();

    int tx = t & 31, ty = t >> 5;
    int ntiles = (n + TM - 1) / TM;

    for (int tile = blockIdx.x; tile < ntiles; tile += gridDim.x) {
        int row0 = tile * TM;
        __syncthreads();                 // prior iter readers done
        // load tile: 64 rows x 256 cols (mean || x), coalesced float4
        for (int i = t; i < 64 * 64; i += 256) {
            int r = i >> 6, c4 = i & 63;
            int grow = row0 + r;
            float4 v = {0.f, 0.f, 0.f, 0.f};
            if (grow < n) {
                const float* src = (c4 < 32)
                    ? (g_mean + (size_t)grow * H + c4 * 4)
                    : (xin    + (size_t)grow * H + (c4 - 32) * 4);
                v = *reinterpret_cast<const float4*>(src);
            }
            *reinterpret_cast<float4*>(sIn + r * 256 + c4 * 4) = v;
        }
        __syncthreads();

        unsigned long long acc[8][2];
        #pragma unroll
        for (int i = 0; i < 8; i++) { acc[i][0] = 0ULL; acc[i][1] = 0ULL; }

        for (int k = 0; k < 256; k += 4) {
            // weights for 4 k-steps: pairs read directly (no packing movs)
            longlong2 w[4];
            #pragma unroll
            for (int kk = 0; kk < 4; kk++)
                w[kk] = *reinterpret_cast<const longlong2*>(sW + (k + kk) * 128 + tx * 4);
            #pragma unroll
            for (int i = 0; i < 8; i++) {
                int r = ty + (i << 3);
                const float4 a = *reinterpret_cast<const float4*>(sIn + r * 256 + k);
                unsigned long long a0 = pk2(a.x, a.x);
                unsigned long long a1 = pk2(a.y, a.y);
                unsigned long long a2 = pk2(a.z, a.z);
                unsigned long long a3 = pk2(a.w, a.w);
                FMA2(acc[i][0], a0, (unsigned long long)w[0].x); FMA2(acc[i][1], a0, (unsigned long long)w[0].y);
                FMA2(acc[i][0], a1, (unsigned long long)w[1].x); FMA2(acc[i][1], a1, (unsigned long long)w[1].y);
                FMA2(acc[i][0], a2, (unsigned long long)w[2].x); FMA2(acc[i][1], a2, (unsigned long long)w[2].y);
                FMA2(acc[i][0], a3, (unsigned long long)w[3].x); FMA2(acc[i][1], a3, (unsigned long long)w[3].y);
            }
        }

        float b0 = sb[tx * 4 + 0], b1 = sb[tx * 4 + 1], b2 = sb[tx * 4 + 2], b3 = sb[tx * 4 + 3];
        #pragma unroll
        for (int i = 0; i < 8; i++) {
            int r = row0 + ty + (i << 3);
            if (r < n) {
                float x0, x1, x2, x3;
                upk2(acc[i][0], x0, x1);
                upk2(acc[i][1], x2, x3);
                float4 o;
                o.x = fmaxf(x0 + b0, 0.f);
                o.y = fmaxf(x1 + b1, 0.f);
                o.z = fmaxf(x2 + b2, 0.f);
                o.w = fmaxf(x3 + b3, 0.f);
                *reinterpret_cast<float4*>(out + (size_t)r * H + tx * 4) = o;
            }
        }
    }
}

// score = tanh( (h . w) / ||w|| ), one warp per node
__global__ void k_score(const float* __restrict__ h, const float* __restrict__ pw, int n) {
    int gid  = blockIdx.x * blockDim.x + threadIdx.x;
    int node = gid >> 5;
    int lane = gid & 31;
    if (node >= n) return;
    float dot = 0.f, wn = 0.f;
    #pragma unroll
    for (int c = lane; c < H; c += 32) {
        float w = pw[c];
        dot += h[(size_t)node * H + c] * w;
        wn  += w * w;
    }
    #pragma unroll
    for (int o = 16; o; o >>= 1) {
        dot += __shfl_down_sync(0xffffffffu, dot, o);
        wn  += __shfl_down_sync(0xffffffffu, wn, o);
    }
    if (lane == 0) g_score[node] = tanhf(dot / sqrtf(wn));
}

// stable top-k per graph via rank counting (matches jax.lax.top_k tie-break)
__global__ void k_topk(int n_per, int k) {
    int b = blockIdx.x;
    __shared__ float s[512];
    int i = threadIdx.x;
    s[i] = (i < n_per) ? g_score[b * n_per + i] : -1e30f;
    __syncthreads();
    if (i < n_per) {
        float si = s[i];
        int rank = 0;
        for (int j = 0; j < n_per; j++) {
            float sj = s[j];
            if (sj > si || (sj == si && j < i)) rank++;
        }
        int old = b * n_per + i;
        if (rank < k) {
            int nw = b * k + rank;
            g_map[old] = nw;
            g_perm[nw] = old;
        } else {
            g_map[old] = -1;
        }
    }
}

__global__ void k_pool(const float* __restrict__ hin, float* __restrict__ hout, int nnew) {
    int gid = blockIdx.x * blockDim.x + threadIdx.x;
    if (gid >= nnew * H) return;
    int j = gid >> 7, c = gid & 127;
    int old = g_perm[j];
    hout[gid] = hin[(size_t)old * H + c] * g_score[old];
}

// remap + compact surviving edges into next layer's arrays
__global__ void k_compact(const int* __restrict__ src, const int* __restrict__ dst,
                          const int* __restrict__ ecnt,
                          int* __restrict__ nsrc, int* __restrict__ ndst,
                          int* __restrict__ necnt) {
    int e = blockIdx.x * blockDim.x + threadIdx.x;
    int n = *ecnt;
    bool act = false;
    int ns = 0, nd = 0;
    if (e < n) {
        ns = g_map[src[e]];
        nd = g_map[dst[e]];
        act = (ns >= 0) && (nd >= 0);
    }
    unsigned mask = __ballot_sync(0xffffffffu, act);
    if (act) {
        int lane = threadIdx.x & 31;
        int leader = __ffs(mask) - 1;
        int base = 0;
        if (lane == leader) base = atomicAdd(necnt, __popc(mask));
        base = __shfl_sync(mask, base, leader);
        int pos = base + __popc(mask & ((1u << lane) - 1u));
        nsrc[pos] = ns;
        ndst[pos] = nd;
    }
}

// z[b] (+)= [max || mean] over k nodes
__global__ void k_readout(const float* __restrict__ h, int k, int acc) {
    int b = blockIdx.x, c = threadIdx.x;
    float mx = -1e30f, sm = 0.f;
    for (int r = 0; r < k; r++) {
        float v = h[(size_t)(b * k + r) * H + c];
        mx = fmaxf(mx, v);
        sm += v;
    }
    float mean = sm / (float)k;
    if (acc) {
        g_z[b * 2 * H + c]     += mx;
        g_z[b * 2 * H + H + c] += mean;
    } else {
        g_z[b * 2 * H + c]     = mx;
        g_z[b * 2 * H + H + c] = mean;
    }
}

// MLP head + log_softmax, one block per graph
__global__ void k_mlp(const float* __restrict__ W1, const float* __restrict__ b1,
                      const float* __restrict__ W2, const float* __restrict__ b2,
                      const float* __restrict__ W3, const float* __restrict__ b3,
                      float* __restrict__ out) {
    int b = blockIdx.x, t = threadIdx.x;
    __shared__ float zin[256], t1[128], t2[64], lg[10];
    zin[t] = g_z[b * 256 + t];
    __syncthreads();
    if (t < 128) {
        float a = b1[t];
        for (int k = 0; k < 256; k++) a += zin[k] * W1[k * 128 + t];
        t1[t] = fmaxf(a, 0.f);
    }
    __syncthreads();
    if (t < 64) {
        float a = b2[t];
        for (int k = 0; k < 128; k++) a += t1[k] * W2[k * 64 + t];
        t2[t] = fmaxf(a, 0.f);
    }
    __syncthreads();
    if (t < 10) {
        float a = b3[t];
        for (int k = 0; k < 64; k++) a += t2[k] * W3[k * 10 + t];
        lg[t] = a;
    }
    __syncthreads();
    if (t == 0) {
        float mx = -1e30f;
        for (int i = 0; i < 10; i++) mx = fmaxf(mx, lg[i]);
        float s = 0.f;
        for (int i = 0; i < 10; i++) s += expf(lg[i] - mx);
        float lse = mx + logf(s);
        for (int i = 0; i < 10; i++) out[b * 10 + i] = lg[i] - lse;
    }
}

// ---------------- host ----------------

static const int SAGE_SMEM = (256 * 128 + 64 * 256 + 128) * sizeof(float);  // 197120 B

extern "C" void kernel_launch(void* const* d_in, const int* in_sizes, int n_in,
                              void* d_out, int out_size) {
    const float* x   = (const float*)d_in[0];
    const int*   ei  = (const int*)  d_in[1];
    const float* Wl1 = (const float*)d_in[2];
    const float* bl1 = (const float*)d_in[3];
    const float* Wr1 = (const float*)d_in[4];
    const float* Wl2 = (const float*)d_in[5];
    const float* bl2 = (const float*)d_in[6];
    const float* Wr2 = (const float*)d_in[7];
    const float* Wl3 = (const float*)d_in[8];
    const float* bl3 = (const float*)d_in[9];
    const float* Wr3 = (const float*)d_in[10];
    const float* pw1 = (const float*)d_in[11];
    const float* pw2 = (const float*)d_in[12];
    const float* pw3 = (const float*)d_in[13];
    const float* W1  = (const float*)d_in[14];
    const float* b1  = (const float*)d_in[15];
    const float* W2  = (const float*)d_in[16];
    const float* b2  = (const float*)d_in[17];
    const float* W3  = (const float*)d_in[18];
    const float* b3  = (const float*)d_in[19];
    float* out = (float*)d_out;

    static bool attr_set = false;
    if (!attr_set) {
        cudaFuncSetAttribute(k_sage, cudaFuncAttributeMaxDynamicSharedMemorySize, SAGE_SMEM);
        attr_set = true;
    }

    void *p_h, *p_mean, *p_p1, *p_p2, *p_srcB, *p_dstB, *p_srcC, *p_dstC, *p_ecnt;
    cudaGetSymbolAddress(&p_h,    g_h);
    cudaGetSymbolAddress(&p_mean, g_mean);
    cudaGetSymbolAddress(&p_p1,   g_p1);
    cudaGetSymbolAddress(&p_p2,   g_p2);
    cudaGetSymbolAddress(&p_srcB, g_srcB);
    cudaGetSymbolAddress(&p_dstB, g_dstB);
    cudaGetSymbolAddress(&p_srcC, g_srcC);
    cudaGetSymbolAddress(&p_dstC, g_dstC);
    cudaGetSymbolAddress(&p_ecnt, g_ecnt);
    float* dh   = (float*)p_h;
    int*   ecnt = (int*)p_ecnt;

    k_init<<<1, 1>>>();

    struct Layer {
        const float *Wl, *bl, *Wr, *pw;
        const int *src, *dst;
        int *ecptr;
        int n_in, n_per, k;
        float* pool_out;
    } layers[3] = {
        {Wl1, bl1, Wr1, pw1, ei,           ei + NE,      ecnt + 0, NN,      NPG, K1, (float*)p_p1},
        {Wl2, bl2, Wr2, pw2, (int*)p_srcB, (int*)p_dstB, ecnt + 1, NB * K1, K1,  K2, (float*)p_p2},
        {Wl3, bl3, Wr3, pw3, (int*)p_srcC, (int*)p_dstC, ecnt + 2, NB * K2, K2,  K3, (float*)p_p1},
    };

    const float* xin = x;
    const int EG = (NE + 255) / 256;   // edge-kernel grid (max size, count-checked)

    for (int l = 0; l < 3; l++) {
        const Layer& L = layers[l];
        int n = L.n_in;

        // CSR build
        k_prep<<<(n + 255) / 256, 256>>>(n);
        k_degree<<<EG, 256>>>(L.dst, L.ecptr);
        k_alloc<<<(n + 255) / 256, 256>>>(n);
        k_fill<<<EG, 256>>>(L.src, L.dst, L.ecptr);

        // mean aggregation (gather)
        k_gather<<<(n * 32 + 255) / 256, 256>>>(xin, n);

        // fused SAGE GEMM
        int ntiles = (n + TM - 1) / TM;
        int grid = ntiles < 148 ? ntiles : 148;
        k_sage<<<grid, 256, SAGE_SMEM>>>(xin, L.Wl, L.bl, L.Wr, dh, n);

        // pooling
        k_score<<<(n * 32 + 255) / 256, 256>>>(dh, L.pw, n);
        k_topk<<<NB, 512>>>(L.n_per, L.k);
        int nnew = NB * L.k;
        k_pool<<<(nnew * H + 255) / 256, 256>>>(dh, L.pool_out, nnew);

        if (l < 2)
            k_compact<<<EG, 256>>>(L.src, L.dst, L.ecptr,
                                   (int*)layers[l + 1].src, (int*)layers[l + 1].dst,
                                   layers[l + 1].ecptr);

        k_readout<<<NB, H>>>(L.pool_out, L.k, l == 0 ? 0 : 1);

        xin = L.pool_out;
    }

    k_mlp<<<NB, 256>>>(W1, b1, W2, b2, W3, b3, out);
}

// round 3
// speedup vs baseline: 2.7637x; 1.0704x over previous
#include <cuda_runtime.h>
#include <math.h>

#define NB   100
#define NPG  500
#define NN   (NB*NPG)     // 50000 nodes
#define NE   (NN*12)      // 600000 edges
#define EPG  (NPG*12)     // 6000 edges per graph (contiguous)
#define H    128
#define K1   250
#define K2   125
#define K3   63

// ---------------- scratch (device globals; no allocation) ----------------
__device__ float g_h    [NN*H];        // pre-pool features
__device__ float g_mean [NN*H];        // gathered mean
__device__ float g_p1   [NB*K1*H];     // pooled buffer A
__device__ float g_p2   [NB*K2*H];     // pooled buffer B
__device__ int   g_srcB [NE];
__device__ int   g_dstB [NE];
__device__ int   g_srcC [NE];
__device__ int   g_dstC [NE];
__device__ int   g_gecB [NB];
__device__ int   g_gecC [NB];
__device__ float g_z    [NB*2*H];

// ---------------- f32x2 helpers ----------------
__device__ __forceinline__ unsigned long long pk2(float x, float y) {
    unsigned long long r;
    asm("mov.b64 %0, {%1, %2};" : "=l"(r) : "r"(__float_as_uint(x)), "r"(__float_as_uint(y)));
    return r;
}
__device__ __forceinline__ void upk2(unsigned long long v, float& x, float& y) {
    unsigned a, b;
    asm("mov.b64 {%0, %1}, %2;" : "=r"(a), "=r"(b) : "l"(v));
    x = __uint_as_float(a); y = __uint_as_float(b);
}
#define FMA2(d, a, b) asm("fma.rn.f32x2 %0, %1, %2, %3;" : "=l"(d) : "l"(a), "l"(b), "l"(d))

// ---------------- kernels ----------------

// One block per graph: smem degree count -> smem scan -> smem CSR fill ->
// gather neighbor means. Replaces 5 kernels of the previous round.
__global__ void __launch_bounds__(512) k_aggregate(
        const int* __restrict__ src, const int* __restrict__ dst,
        const int* __restrict__ gec, int fixed,
        const float* __restrict__ xin, int n_per) {
    extern __shared__ int sm[];
    int* s_src = sm;                 // [EPG]
    int* s_dst = sm + EPG;           // [EPG] (local dst)
    int* s_csr = sm + 2 * EPG;       // [EPG]
    int* s_deg = sm + 3 * EPG;       // [512]
    int* s_st  = s_deg + 512;        // [512] exclusive starts
    int* s_cur = s_st + 512;         // [512] fill cursors

    int b = blockIdx.x, t = threadIdx.x;
    int ne    = fixed ? EPG : gec[b];
    int ebase = b * EPG;
    int nbase = b * n_per;

    s_deg[t] = 0;
    __syncthreads();

    for (int i = t; i < ne; i += blockDim.x) {
        int s = src[ebase + i];
        int d = dst[ebase + i] - nbase;
        s_src[i] = s;
        s_dst[i] = d;
        atomicAdd(&s_deg[d], 1);
    }
    __syncthreads();

    // Hillis-Steele inclusive scan over 512 entries
    int v = s_deg[t];
    s_st[t] = v;
    __syncthreads();
    #pragma unroll
    for (int o = 1; o < 512; o <<= 1) {
        int u = (t >= o) ? s_st[t - o] : 0;
        __syncthreads();
        s_st[t] += u;
        __syncthreads();
    }
    int excl = s_st[t] - v;
    s_st[t]  = excl;
    s_cur[t] = excl;
    __syncthreads();

    for (int i = t; i < ne; i += blockDim.x) {
        int pos = atomicAdd(&s_cur[s_dst[i]], 1);
        s_csr[pos] = s_src[i];
    }
    __syncthreads();

    // gather: warp per node
    int lane = t & 31, wid = t >> 5, nw = blockDim.x >> 5;
    for (int node = wid; node < n_per; node += nw) {
        int deg = s_deg[node], st = s_st[node];
        float4 acc = {0.f, 0.f, 0.f, 0.f};
        for (int j = 0; j < deg; j++) {
            int s = s_csr[st + j];
            float4 vv = reinterpret_cast<const float4*>(xin + (size_t)s * H)[lane];
            acc.x += vv.x; acc.y += vv.y; acc.z += vv.z; acc.w += vv.w;
        }
        float invd = 1.0f / fmaxf((float)deg, 1.0f);
        acc.x *= invd; acc.y *= invd; acc.z *= invd; acc.w *= invd;
        reinterpret_cast<float4*>(g_mean + (size_t)(nbase + node) * H)[lane] = acc;
    }
}

// out = relu( [mean||x] @ [Wl;Wr] + bl ), K=256 fused GEMM, f32x2 packed math
#define TM 64
__global__ void __launch_bounds__(256) k_sage(const float* __restrict__ xin,
                                              const float* __restrict__ Wl,
                                              const float* __restrict__ bl,
                                              const float* __restrict__ Wr,
                                              float* __restrict__ out, int n) {
    extern __shared__ float sh[];
    float* sW  = sh;                    // [256][128]
    float* sIn = sh + 256 * 128;        // [64][256]
    float* sb  = sIn + 64 * 256;        // [128]
    int t = threadIdx.x;
    for (int i = t; i < 128 * 128; i += 256) { sW[i] = Wl[i]; sW[128 * 128 + i] = Wr[i]; }
    if (t < 128) sb[t] = bl[t];
    __syncthreads();

    int tx = t & 31, ty = t >> 5;
    int ntiles = (n + TM - 1) / TM;

    for (int tile = blockIdx.x; tile < ntiles; tile += gridDim.x) {
        int row0 = tile * TM;
        __syncthreads();
        for (int i = t; i < 64 * 64; i += 256) {
            int r = i >> 6, c4 = i & 63;
            int grow = row0 + r;
            float4 v = {0.f, 0.f, 0.f, 0.f};
            if (grow < n) {
                const float* src = (c4 < 32)
                    ? (g_mean + (size_t)grow * H + c4 * 4)
                    : (xin    + (size_t)grow * H + (c4 - 32) * 4);
                v = *reinterpret_cast<const float4*>(src);
            }
            *reinterpret_cast<float4*>(sIn + r * 256 + c4 * 4) = v;
        }
        __syncthreads();

        unsigned long long acc[8][2];
        #pragma unroll
        for (int i = 0; i < 8; i++) { acc[i][0] = 0ULL; acc[i][1] = 0ULL; }

        for (int k = 0; k < 256; k += 4) {
            longlong2 w[4];
            #pragma unroll
            for (int kk = 0; kk < 4; kk++)
                w[kk] = *reinterpret_cast<const longlong2*>(sW + (k + kk) * 128 + tx * 4);
            #pragma unroll
            for (int i = 0; i < 8; i++) {
                int r = ty + (i << 3);
                const float4 a = *reinterpret_cast<const float4*>(sIn + r * 256 + k);
                unsigned long long a0 = pk2(a.x, a.x);
                unsigned long long a1 = pk2(a.y, a.y);
                unsigned long long a2 = pk2(a.z, a.z);
                unsigned long long a3 = pk2(a.w, a.w);
                FMA2(acc[i][0], a0, (unsigned long long)w[0].x); FMA2(acc[i][1], a0, (unsigned long long)w[0].y);
                FMA2(acc[i][0], a1, (unsigned long long)w[1].x); FMA2(acc[i][1], a1, (unsigned long long)w[1].y);
                FMA2(acc[i][0], a2, (unsigned long long)w[2].x); FMA2(acc[i][1], a2, (unsigned long long)w[2].y);
                FMA2(acc[i][0], a3, (unsigned long long)w[3].x); FMA2(acc[i][1], a3, (unsigned long long)w[3].y);
            }
        }

        float b0 = sb[tx * 4 + 0], b1 = sb[tx * 4 + 1], b2 = sb[tx * 4 + 2], b3 = sb[tx * 4 + 3];
        #pragma unroll
        for (int i = 0; i < 8; i++) {
            int r = row0 + ty + (i << 3);
            if (r < n) {
                float x0, x1, x2, x3;
                upk2(acc[i][0], x0, x1);
                upk2(acc[i][1], x2, x3);
                float4 o;
                o.x = fmaxf(x0 + b0, 0.f);
                o.y = fmaxf(x1 + b1, 0.f);
                o.z = fmaxf(x2 + b2, 0.f);
                o.w = fmaxf(x3 + b3, 0.f);
                *reinterpret_cast<float4*>(out + (size_t)r * H + tx * 4) = o;
            }
        }
    }
}

// One block per graph: score + stable top-k + pool + readout + edge compact.
__global__ void __launch_bounds__(512) k_pool_all(
        const float* __restrict__ h, const float* __restrict__ pw,
        int n_per, int k, int layer,
        const int* __restrict__ src, const int* __restrict__ dst,
        const int* __restrict__ gec, int fixed,
        int* __restrict__ nsrc, int* __restrict__ ndst, int* __restrict__ ngec,
        float* __restrict__ hout) {
    __shared__ float s_w[128];
    __shared__ float s_sc[512];
    __shared__ int   s_map[512];
    __shared__ int   s_perm[256];
    __shared__ float s_inv;
    __shared__ int   s_cursor;

    int b = blockIdx.x, t = threadIdx.x;
    int lane = t & 31, wid = t >> 5, nw = blockDim.x >> 5;
    int nbase = b * n_per;

    if (t < 128) s_w[t] = pw[t];
    if (t == 0) s_cursor = 0;
    __syncthreads();

    if (wid == 0) {
        float wn = 0.f;
        #pragma unroll
        for (int c = lane; c < 128; c += 32) { float w = s_w[c]; wn += w * w; }
        #pragma unroll
        for (int o = 16; o; o >>= 1) wn += __shfl_down_sync(0xffffffffu, wn, o);
        if (lane == 0) s_inv = rsqrtf(wn);
    }
    __syncthreads();
    float inv = s_inv;

    // scores: warp per node
    for (int node = wid; node < n_per; node += nw) {
        const float* row = h + (size_t)(nbase + node) * H;
        float dot = 0.f;
        #pragma unroll
        for (int c = lane; c < 128; c += 32) dot += row[c] * s_w[c];
        #pragma unroll
        for (int o = 16; o; o >>= 1) dot += __shfl_down_sync(0xffffffffu, dot, o);
        if (lane == 0) s_sc[node] = tanhf(dot * inv);
    }
    __syncthreads();

    // stable top-k via rank counting (matches jax.lax.top_k tie-break)
    if (t < n_per) {
        float si = s_sc[t];
        int rank = 0;
        for (int j = 0; j < n_per; j++) {
            float sj = s_sc[j];
            rank += (sj > si) || (sj == si && j < t);
        }
        if (rank < k) { s_map[t] = rank; s_perm[rank] = t; }
        else          s_map[t] = -1;
    }
    __syncthreads();

    // pool: warp per kept rank
    for (int r = wid; r < k; r += nw) {
        int node = s_perm[r];
        float sc = s_sc[node];
        float4 v = reinterpret_cast<const float4*>(h + (size_t)(nbase + node) * H)[lane];
        v.x *= sc; v.y *= sc; v.z *= sc; v.w *= sc;
        reinterpret_cast<float4*>(hout + (size_t)(b * k + r) * H)[lane] = v;
    }
    __syncthreads();

    // readout: max||mean over k pooled rows
    if (t < 128) {
        float mx = -1e30f, sm = 0.f;
        for (int r = 0; r < k; r++) {
            float v = hout[(size_t)(b * k + r) * H + t];
            mx = fmaxf(mx, v);
            sm += v;
        }
        float mean = sm / (float)k;
        if (layer == 0) {
            g_z[b * 2 * H + t]     = mx;
            g_z[b * 2 * H + H + t] = mean;
        } else {
            g_z[b * 2 * H + t]     += mx;
            g_z[b * 2 * H + H + t] += mean;
        }
    }

    // edge remap + compact into next layer's per-graph region
    if (layer < 2) {
        int ne = fixed ? EPG : gec[b];
        int ebase = b * EPG;
        for (int e0 = 0; e0 < ne; e0 += blockDim.x) {
            int e = e0 + t;
            int rs = -1, rd = -1;
            if (e < ne) {
                rs = s_map[src[ebase + e] - nbase];
                rd = s_map[dst[ebase + e] - nbase];
            }
            bool act = (rs >= 0) && (rd >= 0);
            unsigned m = __ballot_sync(0xffffffffu, act);
            if (m) {
                int leader = __ffs(m) - 1;
                int base = 0;
                if (lane == leader) base = atomicAdd(&s_cursor, __popc(m));
                base = __shfl_sync(0xffffffffu, base, leader);
                if (act) {
                    int pos = base + __popc(m & ((1u << lane) - 1u));
                    nsrc[ebase + pos] = b * k + rs;
                    ndst[ebase + pos] = b * k + rd;
                }
            }
        }
        __syncthreads();
        if (t == 0) ngec[b] = s_cursor;
    }
}

// MLP head + log_softmax, one block per graph
__global__ void k_mlp(const float* __restrict__ W1, const float* __restrict__ b1,
                      const float* __restrict__ W2, const float* __restrict__ b2,
                      const float* __restrict__ W3, const float* __restrict__ b3,
                      float* __restrict__ out) {
    int b = blockIdx.x, t = threadIdx.x;
    __shared__ float zin[256], t1[128], t2[64], lg[10];
    zin[t] = g_z[b * 256 + t];
    __syncthreads();
    if (t < 128) {
        float a = b1[t];
        for (int k = 0; k < 256; k++) a += zin[k] * W1[k * 128 + t];
        t1[t] = fmaxf(a, 0.f);
    }
    __syncthreads();
    if (t < 64) {
        float a = b2[t];
        for (int k = 0; k < 128; k++) a += t1[k] * W2[k * 64 + t];
        t2[t] = fmaxf(a, 0.f);
    }
    __syncthreads();
    if (t < 10) {
        float a = b3[t];
        for (int k = 0; k < 64; k++) a += t2[k] * W3[k * 10 + t];
        lg[t] = a;
    }
    __syncthreads();
    if (t == 0) {
        float mx = -1e30f;
        for (int i = 0; i < 10; i++) mx = fmaxf(mx, lg[i]);
        float s = 0.f;
        for (int i = 0; i < 10; i++) s += expf(lg[i] - mx);
        float lse = mx + logf(s);
        for (int i = 0; i < 10; i++) out[b * 10 + i] = lg[i] - lse;
    }
}

// ---------------- host ----------------

static const int SAGE_SMEM = (256 * 128 + 64 * 256 + 128) * sizeof(float);  // 197120 B
static const int AGG_SMEM  = (3 * EPG + 3 * 512) * sizeof(int);             // 78144 B

extern "C" void kernel_launch(void* const* d_in, const int* in_sizes, int n_in,
                              void* d_out, int out_size) {
    const float* x   = (const float*)d_in[0];
    const int*   ei  = (const int*)  d_in[1];
    const float* Wl1 = (const float*)d_in[2];
    const float* bl1 = (const float*)d_in[3];
    const float* Wr1 = (const float*)d_in[4];
    const float* Wl2 = (const float*)d_in[5];
    const float* bl2 = (const float*)d_in[6];
    const float* Wr2 = (const float*)d_in[7];
    const float* Wl3 = (const float*)d_in[8];
    const float* bl3 = (const float*)d_in[9];
    const float* Wr3 = (const float*)d_in[10];
    const float* pw1 = (const float*)d_in[11];
    const float* pw2 = (const float*)d_in[12];
    const float* pw3 = (const float*)d_in[13];
    const float* W1  = (const float*)d_in[14];
    const float* b1  = (const float*)d_in[15];
    const float* W2  = (const float*)d_in[16];
    const float* b2  = (const float*)d_in[17];
    const float* W3  = (const float*)d_in[18];
    const float* b3  = (const float*)d_in[19];
    float* out = (float*)d_out;

    static bool attr_set = false;
    if (!attr_set) {
        cudaFuncSetAttribute(k_sage,      cudaFuncAttributeMaxDynamicSharedMemorySize, SAGE_SMEM);
        cudaFuncSetAttribute(k_aggregate, cudaFuncAttributeMaxDynamicSharedMemorySize, AGG_SMEM);
        attr_set = true;
    }

    void *p_h, *p_p1, *p_p2, *p_srcB, *p_dstB, *p_srcC, *p_dstC, *p_gecB, *p_gecC;
    cudaGetSymbolAddress(&p_h,    g_h);
    cudaGetSymbolAddress(&p_p1,   g_p1);
    cudaGetSymbolAddress(&p_p2,   g_p2);
    cudaGetSymbolAddress(&p_srcB, g_srcB);
    cudaGetSymbolAddress(&p_dstB, g_dstB);
    cudaGetSymbolAddress(&p_srcC, g_srcC);
    cudaGetSymbolAddress(&p_dstC, g_dstC);
    cudaGetSymbolAddress(&p_gecB, g_gecB);
    cudaGetSymbolAddress(&p_gecC, g_gecC);
    float* dh = (float*)p_h;

    struct Layer {
        const float *Wl, *bl, *Wr, *pw;
        const int *src, *dst, *gec;   // this layer's edges
        int fixed;
        int *nsrc, *ndst, *ngec;      // next layer's edges
        int n_in, n_per, k;
        float* pool_out;
    } layers[3] = {
        {Wl1, bl1, Wr1, pw1, ei,           ei + NE,      nullptr,       1,
         (int*)p_srcB, (int*)p_dstB, (int*)p_gecB, NN,      NPG, K1, (float*)p_p1},
        {Wl2, bl2, Wr2, pw2, (int*)p_srcB, (int*)p_dstB, (int*)p_gecB,  0,
         (int*)p_srcC, (int*)p_dstC, (int*)p_gecC, NB * K1, K1,  K2, (float*)p_p2},
        {Wl3, bl3, Wr3, pw3, (int*)p_srcC, (int*)p_dstC, (int*)p_gecC,  0,
         nullptr, nullptr, nullptr,                  NB * K2, K2,  K3, (float*)p_p1},
    };

    const float* xin = x;
    for (int l = 0; l < 3; l++) {
        const Layer& L = layers[l];
        int n = L.n_in;

        k_aggregate<<<NB, 512, AGG_SMEM>>>(L.src, L.dst, L.gec, L.fixed, xin, L.n_per);

        int ntiles = (n + TM - 1) / TM;
        int grid = ntiles < 148 ? ntiles : 148;
        k_sage<<<grid, 256, SAGE_SMEM>>>(xin, L.Wl, L.bl, L.Wr, dh, n);

        k_pool_all<<<NB, 512>>>(dh, L.pw, L.n_per, L.k, l,
                                L.src, L.dst, L.gec, L.fixed,
                                L.nsrc, L.ndst, L.ngec, L.pool_out);

        xin = L.pool_out;
    }

    k_mlp<<<NB, 256>>>(W1, b1, W2, b2, W3, b3, out);
}